// round 15
// baseline (speedup 1.0000x reference)
#include <cuda_runtime.h>

// RepeatDecoder: B=1024, S=200, H=128, VOCAB=100000
//   features = tanh(hidden + hidden[:,0:1,:])
//   scores   = features @ w_proj + b_proj ; mask PAD/INTEREST -> -inf
//   attn     = softmax(scores, axis=-1)
//   out[b, input_ids[b,s]] += attn[b,s]   (out zero elsewhere)
//
// R15: fork-join v2. The 61us driver memset runs on a side stream while the
//      cheap SM kernels (score: warp-per-pair; softmax->weights) run on the
//      main stream. Join, then a minimal scatter whose inputs are L2-hot.
//
//        main: [fork] score(12us) -> weights(2us) ----[join]-- scatter(~7us)
//        side:    \-- memset(61us) --------------------/

#define RD_VOCAB 100000
#define RD_PAD_ID (RD_VOCAB - 2)
#define RD_INTEREST_ID (RD_VOCAB - 1)
#define RD_B 1024
#define RD_S 200
#define RD_H 128
#define RD_THREADS 256
#define RD_WARPS (RD_THREADS / 32)
#define RD_PAIRS (RD_B * RD_S / 2)             // 102400 warp-tasks
#define RD_SCORE_BLOCKS (RD_PAIRS / RD_WARPS)  // 12800

// Per-position scores, then per-position weights. 800 KB each, static.
__device__ float g_scores[RD_B * RD_S];
__device__ float g_wgt[RD_B * RD_S];

__device__ __forceinline__ float fast_tanhf(float x) {
    float r;
    asm("tanh.approx.f32 %0, %1;" : "=f"(r) : "f"(x));
    return r;
}

__device__ __forceinline__ float dot_tanh4(const float4 h, const float4 k4,
                                           const float4 w4) {
    float p = fast_tanhf(h.x + k4.x) * w4.x;
    p = fmaf(fast_tanhf(h.y + k4.y), w4.y, p);
    p = fmaf(fast_tanhf(h.z + k4.z), w4.z, p);
    p = fmaf(fast_tanhf(h.w + k4.w), w4.w, p);
    return p;
}

// ---------------------------------------------------------------------------
// Kernel A: scores. One warp per pair (b, s), (b, s+1). No loops; load
// latency amortized by massive block-level parallelism (102400 warps).
// ---------------------------------------------------------------------------
__global__ __launch_bounds__(RD_THREADS)
void rd_score_kernel(const float* __restrict__ hidden,
                     const float* __restrict__ w_proj,
                     const float* __restrict__ b_proj)
{
    const int q    = blockIdx.x * RD_WARPS + (threadIdx.x >> 5);
    const int lane = threadIdx.x & 31;

    const int b = q / (RD_S / 2);           // 100 pairs per batch
    const int s = (q % (RD_S / 2)) * 2;

    const float* hb = hidden + (size_t)b * RD_S * RD_H;

    const float4 k4 = reinterpret_cast<const float4*>(hb)[lane];
    const float4 h0 = __ldcs(&reinterpret_cast<const float4*>(hb + s * RD_H)[lane]);
    const float4 h1 = __ldcs(&reinterpret_cast<const float4*>(hb + (s + 1) * RD_H)[lane]);
    const float4 w4 = reinterpret_cast<const float4*>(w_proj)[lane];
    const float  bias = b_proj[0];

    float p0 = dot_tanh4(h0, k4, w4);
    float p1 = dot_tanh4(h1, k4, w4);

    #pragma unroll
    for (int off = 16; off > 0; off >>= 1) {
        p0 += __shfl_xor_sync(0xFFFFFFFFu, p0, off);
        p1 += __shfl_xor_sync(0xFFFFFFFFu, p1, off);
    }
    if (lane == 0) {
        float2* dst = reinterpret_cast<float2*>(&g_scores[2 * q]); // 2q == b*S+s
        *dst = make_float2(p0 + bias, p1 + bias);
    }
}

// ---------------------------------------------------------------------------
// Kernel B: per-batch softmax over L2-hot scores -> g_wgt. Does NOT touch out
// (runs concurrently with the memset). Also warms ids into L2 for kernel C.
// ---------------------------------------------------------------------------
__global__ __launch_bounds__(RD_THREADS)
void rd_weights_kernel(const int* __restrict__ ids)
{
    __shared__ float s_part[RD_WARPS];
    __shared__ float s_bcast;

    const int b    = blockIdx.x;
    const int tid  = threadIdx.x;
    const int warp = tid >> 5;
    const int lane = tid & 31;

    bool valid = false;
    float my_score = -INFINITY;
    if (tid < RD_S) {
        const int id = ids[(size_t)b * RD_S + tid];
        valid = (id != RD_PAD_ID) && (id != RD_INTEREST_ID);
        if (valid) my_score = g_scores[(size_t)b * RD_S + tid];
    }

    float m = my_score;
    #pragma unroll
    for (int off = 16; off > 0; off >>= 1)
        m = fmaxf(m, __shfl_xor_sync(0xFFFFFFFFu, m, off));
    if (lane == 0) s_part[warp] = m;
    __syncthreads();
    if (warp == 0) {
        float v = (lane < RD_WARPS) ? s_part[lane] : -INFINITY;
        #pragma unroll
        for (int off = 4; off > 0; off >>= 1)
            v = fmaxf(v, __shfl_xor_sync(0xFFFFFFFFu, v, off));
        if (lane == 0) s_bcast = v;
    }
    __syncthreads();
    const float mx = s_bcast;

    const float e = valid ? __expf(my_score - mx) : 0.0f;
    float sum = e;
    #pragma unroll
    for (int off = 16; off > 0; off >>= 1)
        sum += __shfl_xor_sync(0xFFFFFFFFu, sum, off);
    if (lane == 0) s_part[warp] = sum;
    __syncthreads();
    if (warp == 0) {
        float v = (lane < RD_WARPS) ? s_part[lane] : 0.0f;
        #pragma unroll
        for (int off = 4; off > 0; off >>= 1)
            v += __shfl_xor_sync(0xFFFFFFFFu, v, off);
        if (lane == 0) s_bcast = v;
    }
    __syncthreads();

    if (tid < RD_S)
        g_wgt[(size_t)b * RD_S + tid] = e * (1.0f / s_bcast);
}

// ---------------------------------------------------------------------------
// Kernel C: scatter only (post-join). Inputs L2-hot; 200K REDG fire+forget.
// ---------------------------------------------------------------------------
__global__ __launch_bounds__(RD_THREADS)
void rd_scatter_kernel(const int* __restrict__ ids,
                       float* __restrict__ out)
{
    const int i = blockIdx.x * RD_THREADS + threadIdx.x;
    if (i >= RD_B * RD_S) return;
    const int id = ids[i];
    if (id != RD_PAD_ID && id != RD_INTEREST_ID) {
        const int b = i / RD_S;
        atomicAdd(out + (size_t)b * RD_VOCAB + id, g_wgt[i]);
    }
}

extern "C" void kernel_launch(void* const* d_in, const int* in_sizes, int n_in,
                              void* d_out, int out_size)
{
    const float* hidden = (const float*)d_in[0];
    const int*   ids    = (const int*)d_in[1];
    const float* w_proj = (const float*)d_in[2];
    const float* b_proj = (const float*)d_in[3];
    float*       out    = (float*)d_out;

    static cudaStream_t s_side = nullptr;
    static cudaEvent_t  s_evFork = nullptr, s_evJoin = nullptr;
    if (s_side == nullptr) {
        cudaStreamCreateWithFlags(&s_side, cudaStreamNonBlocking);
        cudaEventCreateWithFlags(&s_evFork, cudaEventDisableTiming);
        cudaEventCreateWithFlags(&s_evJoin, cudaEventDisableTiming);
    }

    // Fork: side stream branches off the launch stream.
    cudaEventRecord(s_evFork, 0);
    cudaStreamWaitEvent(s_side, s_evFork, 0);

    // Side: zero the 409.6 MB output via the driver fill path (~6.9 TB/s).
    cudaMemsetAsync(out, 0, (size_t)RD_B * RD_VOCAB * sizeof(float), s_side);

    // Main (concurrent with memset): scores, then softmax weights.
    rd_score_kernel<<<RD_SCORE_BLOCKS, RD_THREADS>>>(hidden, w_proj, b_proj);
    rd_weights_kernel<<<RD_B, RD_THREADS>>>(ids);

    // Join: scatter must see the fully-zeroed output.
    cudaEventRecord(s_evJoin, s_side);
    cudaStreamWaitEvent(0, s_evJoin, 0);

    rd_scatter_kernel<<<(RD_B * RD_S + RD_THREADS - 1) / RD_THREADS, RD_THREADS>>>(ids, out);
}